// round 2
// baseline (speedup 1.0000x reference)
#include <cuda_runtime.h>

// ---------------------------------------------------------------------------
// RecurrentInhibition: y_10 = M x per channel-column, M = A^10 + 0.05*sum A^i,
// A = 0.95 I + 0.05 K (K = banded 27-tap symmetric conv along C=128).
// Exploits exact centrosymmetry of M to halve FLOPs (even/odd folding) and
// Blackwell packed fp32 (fma.rn.f32x2) for 2x fp32 throughput.
// ---------------------------------------------------------------------------

#define CCH   128          // channels
#define HCH   64           // half channels
#define SCOPE 27
#define HALF  13
#define NSTEP 10
#define DECAYF 0.05f
#define PSP   3136         // 56*56 spatial
#define NB    32           // batch
#define TILE_P 32          // spatial tile (3136 = 98*32)
#define NTILE  98
#define JTH   8            // p-thread groups (each owns 4 floats = 2 f32x2 pairs)
#define ITH   16           // i-thread groups (each owns 4 i rows)
#define NTHR  128          // JTH*ITH

// Folded matrices, [k][i] layout (k = reduction index, i = output row 0..63)
__device__ __align__(16) float g_Me[HCH * HCH];
__device__ __align__(16) float g_Mo[HCH * HCH];

// ---------------------------------------------------------------------------
// Precompute: block k computes columns M[:,k] and M[:,127-k] by iterating the
// recurrence on unit vectors, then folds into Me/Mo.
// ---------------------------------------------------------------------------
__global__ void build_M_kernel(const float* __restrict__ w_rec) {
    __shared__ float w[SCOPE];
    __shared__ float2 ybuf[2][CCH];

    const int k = blockIdx.x;    // 0..63
    const int r = threadIdx.x;   // 0..127

    if (r < SCOPE) w[r] = w_rec[r];

    const float2 x0 = make_float2(r == k ? 1.0f : 0.0f,
                                  r == (CCH - 1 - k) ? 1.0f : 0.0f);
    ybuf[0][r] = x0;
    __syncthreads();

    int cur = 0;
    for (int it = 0; it < NSTEP; ++it) {
        float2 acc = make_float2(0.0f, 0.0f);
        #pragma unroll
        for (int t = 0; t < SCOPE; ++t) {
            int j = r + t - HALF;
            if (j >= 0 && j < CCH) {
                float2 yv = ybuf[cur][j];
                acc.x += w[t] * yv.x;
                acc.y += w[t] * yv.y;
            }
        }
        float2 yc = ybuf[cur][r];
        float2 yn;
        yn.x = (1.0f - DECAYF) * yc.x + DECAYF * (x0.x + acc.x);
        yn.y = (1.0f - DECAYF) * yc.y + DECAYF * (x0.y + acc.y);
        ybuf[cur ^ 1][r] = yn;
        __syncthreads();
        cur ^= 1;
    }

    // ybuf[cur][r] = { M[r][k], M[r][127-k] }
    if (r < HCH) {
        float a = ybuf[cur][r].x;
        float b = ybuf[cur][r].y;
        g_Me[k * HCH + r] = 0.5f * (a + b);
        g_Mo[k * HCH + r] = 0.5f * (a - b);
    }
}

// ---------------------------------------------------------------------------
// Packed fp32 helpers (Blackwell f32x2 path; ptxas won't auto-fuse).
// ---------------------------------------------------------------------------
__device__ __forceinline__ void ffma2(unsigned long long& d,
                                      unsigned long long a,
                                      unsigned long long b) {
    asm("fma.rn.f32x2 %0, %1, %2, %0;" : "+l"(d) : "l"(a), "l"(b));
}
__device__ __forceinline__ unsigned long long dup2(float v) {
    unsigned long long r;
    asm("mov.b64 %0, {%1, %1};" : "=l"(r) : "f"(v));
    return r;
}
union U64F2 { unsigned long long u; float2 f; };

// ---------------------------------------------------------------------------
// Main: out[b, :, p] = M @ x[b, :, p], folded form.
//   u[k] = x[k] + x[127-k],  v[k] = x[k] - x[127-k]   (k = 0..63)
//   s[i] = sum_k Me[i][k] u[k],  d[i] = sum_k Mo[i][k] v[k]
//   out[i] = s + d,  out[127-i] = s - d
// ---------------------------------------------------------------------------
__global__ __launch_bounds__(NTHR, 4)
void apply_M_kernel(const float* __restrict__ x, float* __restrict__ out) {
    __shared__ float sX[CCH * TILE_P];     // 16 KB: rows 0..63 = U, row 127-k = V[k]
    __shared__ float sMe[HCH * HCH];       // 16 KB, [k][i]
    __shared__ float sMo[HCH * HCH];       // 16 KB

    const int tid = threadIdx.x;
    const int b   = blockIdx.y;
    const int p0  = blockIdx.x * TILE_P;

    const float* xb = x + (size_t)b * CCH * PSP + p0;

    // ---- matrices first (L2-hot), then X tile (DRAM) ----
    #pragma unroll
    for (int idx = tid; idx < 2048; idx += NTHR) {   // 2 * 1024 float4
        if (idx < 1024) ((float4*)sMe)[idx] = ((const float4*)g_Me)[idx];
        else            ((float4*)sMo)[idx - 1024] = ((const float4*)g_Mo)[idx - 1024];
    }
    #pragma unroll
    for (int idx = tid; idx < CCH * (TILE_P / 4); idx += NTHR) {
        int row = idx >> 3;           // 8 float4 per row
        int c4  = (idx & 7) << 2;
        *(float4*)&sX[row * TILE_P + c4] =
            *(const float4*)(xb + (size_t)row * PSP + c4);
    }
    __syncthreads();

    // ---- in-place even/odd transform: row k <- u, row 127-k <- v ----
    #pragma unroll
    for (int idx = tid; idx < HCH * (TILE_P / 4); idx += NTHR) {
        int k  = idx >> 3;
        int c4 = (idx & 7) << 2;
        float4 a = *(float4*)&sX[k * TILE_P + c4];
        float4 c = *(float4*)&sX[(CCH - 1 - k) * TILE_P + c4];
        float4 u = make_float4(a.x + c.x, a.y + c.y, a.z + c.z, a.w + c.w);
        float4 v = make_float4(a.x - c.x, a.y - c.y, a.z - c.z, a.w - c.w);
        *(float4*)&sX[k * TILE_P + c4] = u;
        *(float4*)&sX[(CCH - 1 - k) * TILE_P + c4] = v;
    }
    __syncthreads();

    // ---- register-tiled GEMM: thread = (itg, jt): 4 i-rows x 2 f32x2 pairs ----
    const int jt  = tid & (JTH - 1);         // p group: floats 4*jt .. 4*jt+3
    const int itg = tid >> 3;                // i group: rows itg*4 .. itg*4+3
    const int i0  = itg * 4;
    const int pc  = 4 * jt;

    unsigned long long accS[4][2], accD[4][2];
    #pragma unroll
    for (int r = 0; r < 4; ++r) {
        accS[r][0] = 0ull; accS[r][1] = 0ull;
        accD[r][0] = 0ull; accD[r][1] = 0ull;
    }

    #pragma unroll 4
    for (int k = 0; k < HCH; ++k) {
        ulonglong2 uu = *(const ulonglong2*)&sX[k * TILE_P + pc];
        ulonglong2 vv = *(const ulonglong2*)&sX[(CCH - 1 - k) * TILE_P + pc];
        float4 me = *(const float4*)&sMe[k * HCH + i0];
        float4 mo = *(const float4*)&sMo[k * HCH + i0];

        unsigned long long m0 = dup2(me.x), m1 = dup2(me.y),
                           m2 = dup2(me.z), m3 = dup2(me.w);
        unsigned long long n0 = dup2(mo.x), n1 = dup2(mo.y),
                           n2 = dup2(mo.z), n3 = dup2(mo.w);

        ffma2(accS[0][0], m0, uu.x);  ffma2(accS[0][1], m0, uu.y);
        ffma2(accS[1][0], m1, uu.x);  ffma2(accS[1][1], m1, uu.y);
        ffma2(accS[2][0], m2, uu.x);  ffma2(accS[2][1], m2, uu.y);
        ffma2(accS[3][0], m3, uu.x);  ffma2(accS[3][1], m3, uu.y);
        ffma2(accD[0][0], n0, vv.x);  ffma2(accD[0][1], n0, vv.y);
        ffma2(accD[1][0], n1, vv.x);  ffma2(accD[1][1], n1, vv.y);
        ffma2(accD[2][0], n2, vv.x);  ffma2(accD[2][1], n2, vv.y);
        ffma2(accD[3][0], n3, vv.x);  ffma2(accD[3][1], n3, vv.y);
    }

    // ---- epilogue: out[i] = s + d, out[127-i] = s - d ----
    float* ob = out + (size_t)b * CCH * PSP + p0 + pc;
    #pragma unroll
    for (int r = 0; r < 4; ++r) {
        int i = i0 + r;
        U64F2 s0, s1, d0, d1;
        s0.u = accS[r][0]; s1.u = accS[r][1];
        d0.u = accD[r][0]; d1.u = accD[r][1];
        float4 top = make_float4(s0.f.x + d0.f.x, s0.f.y + d0.f.y,
                                 s1.f.x + d1.f.x, s1.f.y + d1.f.y);
        float4 bot = make_float4(s0.f.x - d0.f.x, s0.f.y - d0.f.y,
                                 s1.f.x - d1.f.x, s1.f.y - d1.f.y);
        *(float4*)(ob + (size_t)i * PSP)             = top;
        *(float4*)(ob + (size_t)(CCH - 1 - i) * PSP) = bot;
    }
}

// ---------------------------------------------------------------------------
extern "C" void kernel_launch(void* const* d_in, const int* in_sizes, int n_in,
                              void* d_out, int out_size) {
    const float* acts = (const float*)d_in[0];
    const float* w    = (const float*)d_in[1];
    // defensive: handle either metadata ordering
    if (n_in >= 2 && in_sizes[0] == SCOPE) {
        const float* t = acts; acts = w; w = t;
    }
    float* out = (float*)d_out;

    build_M_kernel<<<HCH, CCH>>>(w);
    apply_M_kernel<<<dim3(NTILE, NB), NTHR>>>(acts, out);
}

// round 4
// speedup vs baseline: 1.2308x; 1.2308x over previous
#include <cuda_runtime.h>
#include <cuda_bf16.h>
#include <cstdint>

// ---------------------------------------------------------------------------
// RecurrentInhibition collapsed to y = M x (M = A^10 + 0.05*sum A^i), folded
// by centrosymmetry into two 64x64 GEMMs (S = Me u, D = Mo v), executed on
// tensor cores via bf16 hi/lo split (3-term) mma.sync with fp32 accumulate.
// ---------------------------------------------------------------------------

#define CCH    128
#define HCH    64
#define SCOPE  27
#define HALF   13
#define NSTEP  10
#define DECAYF 0.05f
#define PSP    3136          // 56*56
#define NB     32
#define NP     64            // spatial tile per CTA
#define NPT    49            // 3136 / 64
#define PITCH  72            // bf16 row pitch: 144B = 9*16 (aligned), conflict-free
#define NTHR   256

// Folded matrices in bf16 hi/lo, row-major [i][k], i,k in 0..63
__device__ __nv_bfloat16 g_Aehi[HCH * HCH];
__device__ __nv_bfloat16 g_Aelo[HCH * HCH];
__device__ __nv_bfloat16 g_Aohi[HCH * HCH];
__device__ __nv_bfloat16 g_Aolo[HCH * HCH];

// ---------------------------------------------------------------------------
// Precompute: block k computes M[:,k], M[:,127-k] by iterating the recurrence
// on a unit-vector pair, folds to Me/Mo, splits bf16 hi/lo, stores [i][k].
// ---------------------------------------------------------------------------
__global__ void build_M_kernel(const float* __restrict__ w_rec) {
    __shared__ float w[SCOPE];
    __shared__ float2 ybuf[2][CCH];

    const int k = blockIdx.x;    // 0..63
    const int r = threadIdx.x;   // 0..127

    if (r < SCOPE) w[r] = w_rec[r];

    const float2 x0 = make_float2(r == k ? 1.0f : 0.0f,
                                  r == (CCH - 1 - k) ? 1.0f : 0.0f);
    ybuf[0][r] = x0;
    __syncthreads();

    int cur = 0;
    for (int it = 0; it < NSTEP; ++it) {
        float2 acc = make_float2(0.0f, 0.0f);
        #pragma unroll
        for (int t = 0; t < SCOPE; ++t) {
            int j = r + t - HALF;
            if (j >= 0 && j < CCH) {
                float2 yv = ybuf[cur][j];
                acc.x += w[t] * yv.x;
                acc.y += w[t] * yv.y;
            }
        }
        float2 yc = ybuf[cur][r];
        float2 yn;
        yn.x = (1.0f - DECAYF) * yc.x + DECAYF * (x0.x + acc.x);
        yn.y = (1.0f - DECAYF) * yc.y + DECAYF * (x0.y + acc.y);
        ybuf[cur ^ 1][r] = yn;
        __syncthreads();
        cur ^= 1;
    }

    if (r < HCH) {
        float a = ybuf[cur][r].x;          // M[r][k]
        float b = ybuf[cur][r].y;          // M[r][127-k]
        float me = 0.5f * (a + b);
        float mo = 0.5f * (a - b);
        __nv_bfloat16 mehi = __float2bfloat16_rn(me);
        __nv_bfloat16 melo = __float2bfloat16_rn(me - __bfloat162float(mehi));
        __nv_bfloat16 mohi = __float2bfloat16_rn(mo);
        __nv_bfloat16 molo = __float2bfloat16_rn(mo - __bfloat162float(mohi));
        g_Aehi[r * HCH + k] = mehi;
        g_Aelo[r * HCH + k] = melo;
        g_Aohi[r * HCH + k] = mohi;
        g_Aolo[r * HCH + k] = molo;
    }
}

// ---------------------------------------------------------------------------
// PTX helpers
// ---------------------------------------------------------------------------
__device__ __forceinline__ uint32_t smem_u32(const void* p) {
    uint32_t a;
    asm("{ .reg .u64 t; cvta.to.shared.u64 t, %1; cvt.u32.u64 %0, t; }"
        : "=r"(a) : "l"(p));
    return a;
}
__device__ __forceinline__ void ldsm_x4(uint32_t addr, uint32_t r[4]) {
    asm volatile("ldmatrix.sync.aligned.m8n8.x4.shared.b16 {%0,%1,%2,%3}, [%4];"
                 : "=r"(r[0]), "=r"(r[1]), "=r"(r[2]), "=r"(r[3]) : "r"(addr));
}
__device__ __forceinline__ void ldsm_x4_t(uint32_t addr, uint32_t r[4]) {
    asm volatile("ldmatrix.sync.aligned.m8n8.x4.trans.shared.b16 {%0,%1,%2,%3}, [%4];"
                 : "=r"(r[0]), "=r"(r[1]), "=r"(r[2]), "=r"(r[3]) : "r"(addr));
}
__device__ __forceinline__ void mma_bf16(float d[4], const uint32_t a[4],
                                         uint32_t b0, uint32_t b1) {
    asm volatile(
        "mma.sync.aligned.m16n8k16.row.col.f32.bf16.bf16.f32 "
        "{%0,%1,%2,%3}, {%4,%5,%6,%7}, {%8,%9}, {%0,%1,%2,%3};"
        : "+f"(d[0]), "+f"(d[1]), "+f"(d[2]), "+f"(d[3])
        : "r"(a[0]), "r"(a[1]), "r"(a[2]), "r"(a[3]), "r"(b0), "r"(b1));
}
__device__ __forceinline__ uint32_t pack_bf16(float a, float b) {
    __nv_bfloat162 h = __floats2bfloat162_rn(a, b);   // .x = a (low half)
    return *reinterpret_cast<uint32_t*>(&h);
}

// ---------------------------------------------------------------------------
// Apply kernel: per CTA (b, p-tile of 64):
//   u[k][p] = x[k]+x[127-k], v = x[k]-x[127-k]  (bf16 hi/lo, smem)
//   S = Me u, D = Mo v (3-term bf16-split mma, fp32 acc)
//   out[i] = S+D, out[127-i] = S-D
// ---------------------------------------------------------------------------
__global__ __launch_bounds__(NTHR)
void apply_M_kernel(const float* __restrict__ x, float* __restrict__ out) {
    extern __shared__ __align__(16) unsigned char smem_raw[];
    // 8 tiles of [64][PITCH] bf16 = 9216 B each
    __nv_bfloat16* sAeh = (__nv_bfloat16*)(smem_raw + 0 * 9216);
    __nv_bfloat16* sAel = (__nv_bfloat16*)(smem_raw + 1 * 9216);
    __nv_bfloat16* sAoh = (__nv_bfloat16*)(smem_raw + 2 * 9216);
    __nv_bfloat16* sAol = (__nv_bfloat16*)(smem_raw + 3 * 9216);
    __nv_bfloat16* sUh  = (__nv_bfloat16*)(smem_raw + 4 * 9216);
    __nv_bfloat16* sUl  = (__nv_bfloat16*)(smem_raw + 5 * 9216);
    __nv_bfloat16* sVh  = (__nv_bfloat16*)(smem_raw + 6 * 9216);
    __nv_bfloat16* sVl  = (__nv_bfloat16*)(smem_raw + 7 * 9216);

    const int tid = threadIdx.x;
    const int b   = blockIdx.y;
    const int p0  = blockIdx.x * NP;

    // ---- load folded A matrices (8 KB each) into padded smem ----
    {
        const uint4* srcs[4] = {(const uint4*)g_Aehi, (const uint4*)g_Aelo,
                                (const uint4*)g_Aohi, (const uint4*)g_Aolo};
        __nv_bfloat16* dsts[4] = {sAeh, sAel, sAoh, sAol};
        #pragma unroll
        for (int a4 = 0; a4 < 4; ++a4) {
            const uint4* src = srcs[a4];
            __nv_bfloat16* dst = dsts[a4];
            for (int idx = tid; idx < 512; idx += NTHR) {   // 512 uint4 = 64x64 bf16
                int r  = idx >> 3;
                int cb = (idx & 7) << 3;                    // bf16 col (multiple of 8)
                *(uint4*)&dst[r * PITCH + cb] = src[idx];   // 144B pitch: 16B aligned
            }
        }
    }

    // ---- load X tile, fold to u/v, split bf16 hi/lo ----
    {
        const float* xb = x + (size_t)b * CCH * PSP + p0;
        for (int t = tid; t < 1024; t += NTHR) {            // 64 rows * 16 float4
            int c  = t >> 4;
            int p4 = (t & 15) << 2;
            float4 xt = *(const float4*)(xb + (size_t)c * PSP + p4);
            float4 xm = *(const float4*)(xb + (size_t)(CCH - 1 - c) * PSP + p4);
            float u[4] = {xt.x + xm.x, xt.y + xm.y, xt.z + xm.z, xt.w + xm.w};
            float v[4] = {xt.x - xm.x, xt.y - xm.y, xt.z - xm.z, xt.w - xm.w};
            float uh[4], vh[4];
            uint2 wuh, wul, wvh, wvl;
            #pragma unroll
            for (int e = 0; e < 4; ++e) {
                uh[e] = __bfloat162float(__float2bfloat16_rn(u[e]));
                vh[e] = __bfloat162float(__float2bfloat16_rn(v[e]));
            }
            wuh = make_uint2(pack_bf16(uh[0], uh[1]), pack_bf16(uh[2], uh[3]));
            wul = make_uint2(pack_bf16(u[0] - uh[0], u[1] - uh[1]),
                             pack_bf16(u[2] - uh[2], u[3] - uh[3]));
            wvh = make_uint2(pack_bf16(vh[0], vh[1]), pack_bf16(vh[2], vh[3]));
            wvl = make_uint2(pack_bf16(v[0] - vh[0], v[1] - vh[1]),
                             pack_bf16(v[2] - vh[2], v[3] - vh[3]));
            int off = c * PITCH + p4;                       // bf16 index; 8B aligned
            *(uint2*)&sUh[off] = wuh;
            *(uint2*)&sUl[off] = wul;
            *(uint2*)&sVh[off] = wvh;
            *(uint2*)&sVl[off] = wvl;
        }
    }
    __syncthreads();

    // ---- warp tiling: 8 warps = 4 m-groups (16 i-rows) x 2 n-groups (32 p) ----
    const int wid  = tid >> 5;
    const int lane = tid & 31;
    const int wm   = wid & 3;            // i0 = wm*16
    const int wn   = (wid >> 2) << 5;    // p offset 0 or 32
    const int i0   = wm << 4;

    // ldmatrix per-lane addressing: row = base + (lane&15), col block = (lane>>4)*8
    const int lr = lane & 15;
    const int lc = (lane >> 4) << 3;

    const uint32_t aeh_b = smem_u32(&sAeh[(i0 + lr) * PITCH + lc]);
    const uint32_t ael_b = smem_u32(&sAel[(i0 + lr) * PITCH + lc]);
    const uint32_t aoh_b = smem_u32(&sAoh[(i0 + lr) * PITCH + lc]);
    const uint32_t aol_b = smem_u32(&sAol[(i0 + lr) * PITCH + lc]);
    // B: k-row = kk*16 + (lane&15), n = n0 + (lane>>4)*8; two n0: wn, wn+16
    const uint32_t uh_b0 = smem_u32(&sUh[lr * PITCH + wn + lc]);
    const uint32_t uh_b1 = smem_u32(&sUh[lr * PITCH + wn + 16 + lc]);
    const uint32_t ul_b0 = smem_u32(&sUl[lr * PITCH + wn + lc]);
    const uint32_t ul_b1 = smem_u32(&sUl[lr * PITCH + wn + 16 + lc]);
    const uint32_t vh_b0 = smem_u32(&sVh[lr * PITCH + wn + lc]);
    const uint32_t vh_b1 = smem_u32(&sVh[lr * PITCH + wn + 16 + lc]);
    const uint32_t vl_b0 = smem_u32(&sVl[lr * PITCH + wn + lc]);
    const uint32_t vl_b1 = smem_u32(&sVl[lr * PITCH + wn + 16 + lc]);

    float accS[4][4], accD[4][4];
    #pragma unroll
    for (int j = 0; j < 4; ++j)
        #pragma unroll
        for (int e = 0; e < 4; ++e) { accS[j][e] = 0.0f; accD[j][e] = 0.0f; }

    #pragma unroll
    for (int kk = 0; kk < 4; ++kk) {
        const uint32_t adelta = kk * 32;                 // 16 bf16 along k
        const uint32_t bdelta = kk * 16 * PITCH * 2;     // 16 k-rows

        uint32_t aeh[4], ael[4], aoh[4], aol[4];
        ldsm_x4(aeh_b + adelta, aeh);
        ldsm_x4(ael_b + adelta, ael);
        ldsm_x4(aoh_b + adelta, aoh);
        ldsm_x4(aol_b + adelta, aol);

        uint32_t uh[8], ul[8], vh[8], vl[8];
        ldsm_x4_t(uh_b0 + bdelta, uh);     ldsm_x4_t(uh_b1 + bdelta, uh + 4);
        ldsm_x4_t(ul_b0 + bdelta, ul);     ldsm_x4_t(ul_b1 + bdelta, ul + 4);
        ldsm_x4_t(vh_b0 + bdelta, vh);     ldsm_x4_t(vh_b1 + bdelta, vh + 4);
        ldsm_x4_t(vl_b0 + bdelta, vl);     ldsm_x4_t(vl_b1 + bdelta, vl + 4);

        #pragma unroll
        for (int j = 0; j < 4; ++j) {
            const int bi = ((j >> 1) << 2) + ((j & 1) << 1);   // b0 index
            mma_bf16(accS[j], aeh, uh[bi], uh[bi + 1]);
            mma_bf16(accS[j], aeh, ul[bi], ul[bi + 1]);
            mma_bf16(accS[j], ael, uh[bi], uh[bi + 1]);
            mma_bf16(accD[j], aoh, vh[bi], vh[bi + 1]);
            mma_bf16(accD[j], aoh, vl[bi], vl[bi + 1]);
            mma_bf16(accD[j], aol, vh[bi], vh[bi + 1]);
        }
    }

    // ---- epilogue: out[i] = S+D, out[127-i] = S-D ----
    const int g  = lane >> 2;
    const int tg = lane & 3;
    float* ob = out + (size_t)b * CCH * PSP + p0;
    #pragma unroll
    for (int j = 0; j < 4; ++j) {
        const int p = wn + (j << 3) + (tg << 1);
        const int ia = i0 + g;        // rows for d0,d1
        const int ib = ia + 8;        // rows for d2,d3
        float2 t0 = make_float2(accS[j][0] + accD[j][0], accS[j][1] + accD[j][1]);
        float2 b0 = make_float2(accS[j][0] - accD[j][0], accS[j][1] - accD[j][1]);
        float2 t1 = make_float2(accS[j][2] + accD[j][2], accS[j][3] + accD[j][3]);
        float2 b1 = make_float2(accS[j][2] - accD[j][2], accS[j][3] - accD[j][3]);
        *(float2*)(ob + (size_t)ia * PSP + p)              = t0;
        *(float2*)(ob + (size_t)(CCH - 1 - ia) * PSP + p)  = b0;
        *(float2*)(ob + (size_t)ib * PSP + p)              = t1;
        *(float2*)(ob + (size_t)(CCH - 1 - ib) * PSP + p)  = b1;
    }
}

// ---------------------------------------------------------------------------
extern "C" void kernel_launch(void* const* d_in, const int* in_sizes, int n_in,
                              void* d_out, int out_size) {
    const float* acts = (const float*)d_in[0];
    const float* w    = (const float*)d_in[1];
    if (n_in >= 2 && in_sizes[0] == SCOPE) {  // defensive input ordering
        const float* t = acts; acts = w; w = t;
    }
    float* out = (float*)d_out;

    // Unconditional (no static guards per harness rules); idempotent and
    // executes immediately — safe under graph capture.
    cudaFuncSetAttribute(apply_M_kernel,
                         cudaFuncAttributeMaxDynamicSharedMemorySize, 8 * 9216);

    build_M_kernel<<<HCH, CCH>>>(w);
    apply_M_kernel<<<dim3(NPT, NB), NTHR, 8 * 9216>>>(acts, out);
}

// round 6
// speedup vs baseline: 1.4545x; 1.1818x over previous
#include <cuda_runtime.h>
#include <cuda_bf16.h>
#include <cstdint>

// ---------------------------------------------------------------------------
// RecurrentInhibition collapsed to y = M x (M = A^10 + 0.05*sum A^i), folded
// by centrosymmetry into two 64x64 GEMMs (S = Me u, D = Mo v), executed on
// tensor cores via bf16 hi/lo split (3-term) mma.sync with fp32 accumulate.
// R5: latency-hiding prologue (front-batched LDG, cp.async A tiles, 2 batch
// tiles per CTA with X prefetch under the mma phase).
// ---------------------------------------------------------------------------

#define CCH    128
#define HCH    64
#define SCOPE  27
#define HALF   13
#define NSTEP  10
#define DECAYF 0.05f
#define PSP    3136          // 56*56
#define NB     32
#define NP     64            // spatial tile per CTA
#define NPT    49            // 3136 / 64
#define PITCH  72            // bf16 row pitch: 144B = 9*16 (aligned), conflict-free
#define NTHR   256

// Folded matrices in bf16 hi/lo, row-major [i][k], i,k in 0..63
__device__ __align__(16) __nv_bfloat16 g_Aehi[HCH * HCH];
__device__ __align__(16) __nv_bfloat16 g_Aelo[HCH * HCH];
__device__ __align__(16) __nv_bfloat16 g_Aohi[HCH * HCH];
__device__ __align__(16) __nv_bfloat16 g_Aolo[HCH * HCH];

// ---------------------------------------------------------------------------
// Precompute: block k computes M[:,k], M[:,127-k] by iterating the recurrence
// on a unit-vector pair, folds to Me/Mo, splits bf16 hi/lo, stores [i][k].
// ---------------------------------------------------------------------------
__global__ void build_M_kernel(const float* __restrict__ w_rec) {
    __shared__ float w[SCOPE];
    __shared__ float2 ybuf[2][CCH];

    const int k = blockIdx.x;    // 0..63
    const int r = threadIdx.x;   // 0..127

    if (r < SCOPE) w[r] = w_rec[r];

    const float2 x0 = make_float2(r == k ? 1.0f : 0.0f,
                                  r == (CCH - 1 - k) ? 1.0f : 0.0f);
    ybuf[0][r] = x0;
    __syncthreads();

    int cur = 0;
    for (int it = 0; it < NSTEP; ++it) {
        float2 acc = make_float2(0.0f, 0.0f);
        #pragma unroll
        for (int t = 0; t < SCOPE; ++t) {
            int j = r + t - HALF;
            if (j >= 0 && j < CCH) {
                float2 yv = ybuf[cur][j];
                acc.x += w[t] * yv.x;
                acc.y += w[t] * yv.y;
            }
        }
        float2 yc = ybuf[cur][r];
        float2 yn;
        yn.x = (1.0f - DECAYF) * yc.x + DECAYF * (x0.x + acc.x);
        yn.y = (1.0f - DECAYF) * yc.y + DECAYF * (x0.y + acc.y);
        ybuf[cur ^ 1][r] = yn;
        __syncthreads();
        cur ^= 1;
    }

    if (r < HCH) {
        float a = ybuf[cur][r].x;          // M[r][k]
        float b = ybuf[cur][r].y;          // M[r][127-k]
        float me = 0.5f * (a + b);
        float mo = 0.5f * (a - b);
        __nv_bfloat16 mehi = __float2bfloat16_rn(me);
        __nv_bfloat16 melo = __float2bfloat16_rn(me - __bfloat162float(mehi));
        __nv_bfloat16 mohi = __float2bfloat16_rn(mo);
        __nv_bfloat16 molo = __float2bfloat16_rn(mo - __bfloat162float(mohi));
        g_Aehi[r * HCH + k] = mehi;
        g_Aelo[r * HCH + k] = melo;
        g_Aohi[r * HCH + k] = mohi;
        g_Aolo[r * HCH + k] = molo;
    }
}

// ---------------------------------------------------------------------------
// PTX helpers
// ---------------------------------------------------------------------------
__device__ __forceinline__ uint32_t smem_u32(const void* p) {
    uint32_t a;
    asm("{ .reg .u64 t; cvta.to.shared.u64 t, %1; cvt.u32.u64 %0, t; }"
        : "=r"(a) : "l"(p));
    return a;
}
__device__ __forceinline__ void cp_async16(uint32_t dst, const void* src) {
    asm volatile("cp.async.cg.shared.global [%0], [%1], 16;"
                 :: "r"(dst), "l"(src));
}
__device__ __forceinline__ void cp_async_commit() {
    asm volatile("cp.async.commit_group;");
}
__device__ __forceinline__ void cp_async_wait0() {
    asm volatile("cp.async.wait_group 0;");
}
__device__ __forceinline__ void ldsm_x4(uint32_t addr, uint32_t r[4]) {
    asm volatile("ldmatrix.sync.aligned.m8n8.x4.shared.b16 {%0,%1,%2,%3}, [%4];"
                 : "=r"(r[0]), "=r"(r[1]), "=r"(r[2]), "=r"(r[3]) : "r"(addr));
}
__device__ __forceinline__ void ldsm_x4_t(uint32_t addr, uint32_t r[4]) {
    asm volatile("ldmatrix.sync.aligned.m8n8.x4.trans.shared.b16 {%0,%1,%2,%3}, [%4];"
                 : "=r"(r[0]), "=r"(r[1]), "=r"(r[2]), "=r"(r[3]) : "r"(addr));
}
__device__ __forceinline__ void mma_bf16(float d[4], const uint32_t a[4],
                                         uint32_t b0, uint32_t b1) {
    asm volatile(
        "mma.sync.aligned.m16n8k16.row.col.f32.bf16.bf16.f32 "
        "{%0,%1,%2,%3}, {%4,%5,%6,%7}, {%8,%9}, {%0,%1,%2,%3};"
        : "+f"(d[0]), "+f"(d[1]), "+f"(d[2]), "+f"(d[3])
        : "r"(a[0]), "r"(a[1]), "r"(a[2]), "r"(a[3]), "r"(b0), "r"(b1));
}
__device__ __forceinline__ uint32_t pack_bf16(float a, float b) {
    __nv_bfloat162 h = __floats2bfloat162_rn(a, b);   // .x = a (low half)
    return *reinterpret_cast<uint32_t*>(&h);
}

// ---------------------------------------------------------------------------
// Fold registers (xt = x rows c, xm = mirror rows 127-c) into bf16 hi/lo smem.
// ---------------------------------------------------------------------------
__device__ __forceinline__ void fold_store(const float4 xt[4], const float4 xm[4],
                                           int c0, int p4,
                                           __nv_bfloat16* sUh, __nv_bfloat16* sUl,
                                           __nv_bfloat16* sVh, __nv_bfloat16* sVl) {
    #pragma unroll
    for (int it = 0; it < 4; ++it) {
        const int c = c0 + (it << 4);
        float u[4] = {xt[it].x + xm[it].x, xt[it].y + xm[it].y,
                      xt[it].z + xm[it].z, xt[it].w + xm[it].w};
        float v[4] = {xt[it].x - xm[it].x, xt[it].y - xm[it].y,
                      xt[it].z - xm[it].z, xt[it].w - xm[it].w};
        float uh[4], vh[4];
        #pragma unroll
        for (int e = 0; e < 4; ++e) {
            uh[e] = __bfloat162float(__float2bfloat16_rn(u[e]));
            vh[e] = __bfloat162float(__float2bfloat16_rn(v[e]));
        }
        uint2 wuh = make_uint2(pack_bf16(uh[0], uh[1]), pack_bf16(uh[2], uh[3]));
        uint2 wul = make_uint2(pack_bf16(u[0] - uh[0], u[1] - uh[1]),
                               pack_bf16(u[2] - uh[2], u[3] - uh[3]));
        uint2 wvh = make_uint2(pack_bf16(vh[0], vh[1]), pack_bf16(vh[2], vh[3]));
        uint2 wvl = make_uint2(pack_bf16(v[0] - vh[0], v[1] - vh[1]),
                               pack_bf16(v[2] - vh[2], v[3] - vh[3]));
        const int off = c * PITCH + p4;
        *(uint2*)&sUh[off] = wuh;
        *(uint2*)&sUl[off] = wul;
        *(uint2*)&sVh[off] = wvh;
        *(uint2*)&sVl[off] = wvl;
    }
}

// ---------------------------------------------------------------------------
// MMA phase + epilogue for one tile (identical math to round-4 kernel).
// ---------------------------------------------------------------------------
__device__ __forceinline__ void mma_tile(
    const __nv_bfloat16* sAeh, const __nv_bfloat16* sAel,
    const __nv_bfloat16* sAoh, const __nv_bfloat16* sAol,
    const __nv_bfloat16* sUh,  const __nv_bfloat16* sUl,
    const __nv_bfloat16* sVh,  const __nv_bfloat16* sVl,
    int i0, int wn, int lane, float* ob /* out + b*CCH*PSP + p0 */) {

    const int lr = lane & 15;
    const int lc = (lane >> 4) << 3;

    const uint32_t aeh_b = smem_u32(&sAeh[(i0 + lr) * PITCH + lc]);
    const uint32_t ael_b = smem_u32(&sAel[(i0 + lr) * PITCH + lc]);
    const uint32_t aoh_b = smem_u32(&sAoh[(i0 + lr) * PITCH + lc]);
    const uint32_t aol_b = smem_u32(&sAol[(i0 + lr) * PITCH + lc]);
    const uint32_t uh_b0 = smem_u32(&sUh[lr * PITCH + wn + lc]);
    const uint32_t uh_b1 = smem_u32(&sUh[lr * PITCH + wn + 16 + lc]);
    const uint32_t ul_b0 = smem_u32(&sUl[lr * PITCH + wn + lc]);
    const uint32_t ul_b1 = smem_u32(&sUl[lr * PITCH + wn + 16 + lc]);
    const uint32_t vh_b0 = smem_u32(&sVh[lr * PITCH + wn + lc]);
    const uint32_t vh_b1 = smem_u32(&sVh[lr * PITCH + wn + 16 + lc]);
    const uint32_t vl_b0 = smem_u32(&sVl[lr * PITCH + wn + lc]);
    const uint32_t vl_b1 = smem_u32(&sVl[lr * PITCH + wn + 16 + lc]);

    float accS[4][4], accD[4][4];
    #pragma unroll
    for (int j = 0; j < 4; ++j)
        #pragma unroll
        for (int e = 0; e < 4; ++e) { accS[j][e] = 0.0f; accD[j][e] = 0.0f; }

    #pragma unroll
    for (int kk = 0; kk < 4; ++kk) {
        const uint32_t adelta = kk * 32;                 // 16 bf16 along k
        const uint32_t bdelta = kk * 16 * PITCH * 2;     // 16 k-rows

        uint32_t aeh[4], ael[4], aoh[4], aol[4];
        ldsm_x4(aeh_b + adelta, aeh);
        ldsm_x4(ael_b + adelta, ael);
        ldsm_x4(aoh_b + adelta, aoh);
        ldsm_x4(aol_b + adelta, aol);

        uint32_t uh[8], ul[8], vh[8], vl[8];
        ldsm_x4_t(uh_b0 + bdelta, uh);     ldsm_x4_t(uh_b1 + bdelta, uh + 4);
        ldsm_x4_t(ul_b0 + bdelta, ul);     ldsm_x4_t(ul_b1 + bdelta, ul + 4);
        ldsm_x4_t(vh_b0 + bdelta, vh);     ldsm_x4_t(vh_b1 + bdelta, vh + 4);
        ldsm_x4_t(vl_b0 + bdelta, vl);     ldsm_x4_t(vl_b1 + bdelta, vl + 4);

        #pragma unroll
        for (int j = 0; j < 4; ++j) {
            const int bi = ((j >> 1) << 2) + ((j & 1) << 1);
            mma_bf16(accS[j], aeh, uh[bi], uh[bi + 1]);
            mma_bf16(accS[j], aeh, ul[bi], ul[bi + 1]);
            mma_bf16(accS[j], ael, uh[bi], uh[bi + 1]);
            mma_bf16(accD[j], aoh, vh[bi], vh[bi + 1]);
            mma_bf16(accD[j], aoh, vl[bi], vl[bi + 1]);
            mma_bf16(accD[j], aol, vh[bi], vh[bi + 1]);
        }
    }

    // epilogue: out[i] = S+D, out[127-i] = S-D
    const int g  = lane >> 2;
    const int tg = lane & 3;
    #pragma unroll
    for (int j = 0; j < 4; ++j) {
        const int p = wn + (j << 3) + (tg << 1);
        const int ia = i0 + g;
        const int ib = ia + 8;
        float2 t0 = make_float2(accS[j][0] + accD[j][0], accS[j][1] + accD[j][1]);
        float2 b0 = make_float2(accS[j][0] - accD[j][0], accS[j][1] - accD[j][1]);
        float2 t1 = make_float2(accS[j][2] + accD[j][2], accS[j][3] + accD[j][3]);
        float2 b1 = make_float2(accS[j][2] - accD[j][2], accS[j][3] - accD[j][3]);
        *(float2*)(ob + (size_t)ia * PSP + p)              = t0;
        *(float2*)(ob + (size_t)(CCH - 1 - ia) * PSP + p)  = b0;
        *(float2*)(ob + (size_t)ib * PSP + p)              = t1;
        *(float2*)(ob + (size_t)(CCH - 1 - ib) * PSP + p)  = b1;
    }
}

// ---------------------------------------------------------------------------
// Apply kernel: CTA = (p-tile, batch pair). Processes batches b0, b0+1 with
// the same p-tile: A loaded once (cp.async), X1 front-batched LDG, X2 LDGs
// issued before tile-1 mma so their latency hides under tensor work.
// ---------------------------------------------------------------------------
__global__ __launch_bounds__(NTHR)
void apply_M_kernel(const float* __restrict__ x, float* __restrict__ out) {
    extern __shared__ __align__(16) unsigned char smem_raw[];
    __nv_bfloat16* sAeh = (__nv_bfloat16*)(smem_raw + 0 * 9216);
    __nv_bfloat16* sAel = (__nv_bfloat16*)(smem_raw + 1 * 9216);
    __nv_bfloat16* sAoh = (__nv_bfloat16*)(smem_raw + 2 * 9216);
    __nv_bfloat16* sAol = (__nv_bfloat16*)(smem_raw + 3 * 9216);
    __nv_bfloat16* sUh  = (__nv_bfloat16*)(smem_raw + 4 * 9216);
    __nv_bfloat16* sUl  = (__nv_bfloat16*)(smem_raw + 5 * 9216);
    __nv_bfloat16* sVh  = (__nv_bfloat16*)(smem_raw + 6 * 9216);
    __nv_bfloat16* sVl  = (__nv_bfloat16*)(smem_raw + 7 * 9216);

    const int tid = threadIdx.x;
    const int b0  = blockIdx.y << 1;
    const int p0  = blockIdx.x * NP;

    const float* xb0 = x + (size_t)b0 * CCH * PSP + p0;
    const float* xb1 = xb0 + (size_t)CCH * PSP;

    const int c0 = tid >> 4;            // row group 0..15
    const int p4 = (tid & 15) << 2;     // spatial float offset

    // ---- X1: all 8 LDG.128 issued first (MLP=8, one DRAM round trip) ----
    float4 xt[4], xm[4];
    #pragma unroll
    for (int it = 0; it < 4; ++it) {
        const int c = c0 + (it << 4);
        xt[it] = *(const float4*)(xb0 + (size_t)c * PSP + p4);
        xm[it] = *(const float4*)(xb0 + (size_t)(CCH - 1 - c) * PSP + p4);
    }

    // ---- A tiles via cp.async (L2-hot; issued after DRAM-critical X) ----
    {
        const __nv_bfloat16* srcs[4] = {g_Aehi, g_Aelo, g_Aohi, g_Aolo};
        __nv_bfloat16* dsts[4] = {sAeh, sAel, sAoh, sAol};
        #pragma unroll
        for (int a4 = 0; a4 < 4; ++a4) {
            #pragma unroll
            for (int i = 0; i < 2; ++i) {
                const int idx = tid + (i << 8);        // 0..511
                const int r   = idx >> 3;
                const int cb  = (idx & 7) << 3;
                cp_async16(smem_u32(&dsts[a4][r * PITCH + cb]),
                           srcs[a4] + (idx << 3));
            }
        }
        cp_async_commit();
    }

    fold_store(xt, xm, c0, p4, sUh, sUl, sVh, sVl);
    cp_async_wait0();
    __syncthreads();

    // ---- prefetch X2 before mma: latency hides under tensor phase ----
    #pragma unroll
    for (int it = 0; it < 4; ++it) {
        const int c = c0 + (it << 4);
        xt[it] = *(const float4*)(xb1 + (size_t)c * PSP + p4);
        xm[it] = *(const float4*)(xb1 + (size_t)(CCH - 1 - c) * PSP + p4);
    }

    const int wid  = tid >> 5;
    const int lane = tid & 31;
    const int i0   = (wid & 3) << 4;
    const int wn   = (wid >> 2) << 5;

    // ---- tile 1 ----
    mma_tile(sAeh, sAel, sAoh, sAol, sUh, sUl, sVh, sVl,
             i0, wn, lane, out + (size_t)b0 * CCH * PSP + p0);
    __syncthreads();     // all warps done reading U/V before overwrite

    // ---- tile 2 ----
    fold_store(xt, xm, c0, p4, sUh, sUl, sVh, sVl);
    __syncthreads();
    mma_tile(sAeh, sAel, sAoh, sAol, sUh, sUl, sVh, sVl,
             i0, wn, lane, out + (size_t)(b0 + 1) * CCH * PSP + p0);
}

// ---------------------------------------------------------------------------
extern "C" void kernel_launch(void* const* d_in, const int* in_sizes, int n_in,
                              void* d_out, int out_size) {
    const float* acts = (const float*)d_in[0];
    const float* w    = (const float*)d_in[1];
    if (n_in >= 2 && in_sizes[0] == SCOPE) {  // defensive input ordering
        const float* t = acts; acts = w; w = t;
    }
    float* out = (float*)d_out;

    cudaFuncSetAttribute(apply_M_kernel,
                         cudaFuncAttributeMaxDynamicSharedMemorySize, 8 * 9216);

    build_M_kernel<<<HCH, CCH>>>(w);
    apply_M_kernel<<<dim3(NPT, NB / 2), NTHR, 8 * 9216>>>(acts, out);
}